// round 2
// baseline (speedup 1.0000x reference)
#include <cuda_runtime.h>
#include <math.h>

#define T   128
#define H   1024
#define IN  4096
#define NE  8

typedef unsigned long long u64;

// ---------------- device-global scratch (no runtime allocation) ----------------
__device__ int   g_cnt[NE];
__device__ int   g_tok[NE][T];
__device__ float g_coef[NE][T];
__device__ float g_act[NE][T][IN];   // 16.8 MB fp32 scratch for swiglu activations

// ---------------- packed fp32x2 helpers (FFMA2 path — 2x fp32 throughput) ------
__device__ __forceinline__ void ffma2(u64 &acc, u64 a, u64 b) {
    asm("fma.rn.f32x2 %0, %1, %2, %0;" : "+l"(acc) : "l"(a), "l"(b));
}
__device__ __forceinline__ u64 pack2(float x, float y) {
    u64 r; asm("mov.b64 %0, {%1, %2};" : "=l"(r) : "f"(x), "f"(y)); return r;
}
__device__ __forceinline__ float2 unpack2(u64 v) {
    float2 r; asm("mov.b64 {%0, %1}, %2;" : "=f"(r.x), "=f"(r.y) : "l"(v)); return r;
}

// ---------------- kernel 0: zero the output ----------------
__global__ void zero_out_kernel(float* __restrict__ out) {
    int i = blockIdx.x * blockDim.x + threadIdx.x;
    if (i < T * H) out[i] = 0.0f;
}

// ---------------- kernel 1: routing (top-2 + renormalize, build expert lists) ----
__global__ void route_kernel(const float* __restrict__ routing) {
    __shared__ int s_cnt[NE];
    int t = threadIdx.x;
    if (t < NE) s_cnt[t] = 0;
    __syncthreads();

    float r[NE];
#pragma unroll
    for (int e = 0; e < NE; e++) r[e] = routing[t * NE + e];

    // top-1 (lowest index wins ties via strict >)
    int i0 = 0;
#pragma unroll
    for (int e = 1; e < NE; e++) if (r[e] > r[i0]) i0 = e;
    // top-2
    int i1 = (i0 == 0) ? 1 : 0;
#pragma unroll
    for (int e = 0; e < NE; e++) if (e != i0 && r[e] > r[i1]) i1 = e;

    // softmax + renormalize over top-2 collapses to a 2-way sigmoid
    float d  = expf(r[i1] - r[i0]);   // <= 1
    float s0 = 1.0f / (1.0f + d);
    float s1 = d / (1.0f + d);

    int p0 = atomicAdd(&s_cnt[i0], 1);
    int p1 = atomicAdd(&s_cnt[i1], 1);
    g_tok[i0][p0]  = t;  g_coef[i0][p0] = s0;
    g_tok[i1][p1]  = t;  g_coef[i1][p1] = s1;

    __syncthreads();
    if (t < NE) g_cnt[t] = s_cnt[t];
}

// ---------------- kernel 2: fc1 + swiglu --------------------------------------
// grid: (IN/64, ceil(T/32), NE), block 256
// BM=32 tokens, BN=64 inter channels (=> 128 weight rows: up + gate), BK=32.
// Shared tiles are k-major so the compute loop is conflict-free:
//   per k per thread: 1 LDS.128 (x, broadcast) + 2 LDS.64 (wu, wg) + 4 packs + 8 FFMA2
__global__ __launch_bounds__(256) void fc1_kernel(const float* __restrict__ x,
                                                  const float* __restrict__ w1) {
    int e   = blockIdx.z;
    int cnt = g_cnt[e];
    int m0  = blockIdx.y * 32;
    if (m0 >= cnt) return;
    int n0  = blockIdx.x * 64;

    __shared__ __align__(16) float Xs[32][36];   // [k][m]
    __shared__ __align__(16) float Wu[32][68];   // [k][n]  (up rows n0..n0+63)
    __shared__ __align__(16) float Wg[32][68];   // [k][n]  (gate rows IN+n0..)
    __shared__ int toks[32];

    int tid = threadIdx.x;
    if (tid < 32) toks[tid] = (m0 + tid < cnt) ? g_tok[e][m0 + tid] : -1;
    __syncthreads();

    const float* w1e = w1 + (size_t)e * (2 * IN) * H;

    // loader roles
    int xrow = tid >> 3;            // m: 0..31
    int xk4  = (tid & 7) * 4;       // k: 0,4,...,28
    int xtok = toks[xrow];
    const float* xsrc = (xtok >= 0) ? (x + (size_t)xtok * H + xk4) : 0;

    int wrow = tid >> 2;            // n: 0..63
    int wk0  = (tid & 3) * 4;       // k: loads wk0 and wk0+16
    const float* usrc = w1e + (size_t)(n0 + wrow) * H + wk0;
    const float* gsrc = w1e + (size_t)(IN + n0 + wrow) * H + wk0;

    // compute roles
    int mg = tid >> 5;              // warp id -> m group (4 tokens)
    int ng = tid & 31;              // n pair: n = 2ng, 2ng+1

    u64 au[4] = {0ull, 0ull, 0ull, 0ull};
    u64 ag[4] = {0ull, 0ull, 0ull, 0ull};

    for (int k0 = 0; k0 < H; k0 += 32) {
        float4 xv = make_float4(0.f, 0.f, 0.f, 0.f);
        if (xsrc) xv = *(const float4*)(xsrc + k0);
        float4 u0 = *(const float4*)(usrc + k0);
        float4 u1 = *(const float4*)(usrc + k0 + 16);
        float4 g0 = *(const float4*)(gsrc + k0);
        float4 g1 = *(const float4*)(gsrc + k0 + 16);

        Xs[xk4 + 0][xrow] = xv.x; Xs[xk4 + 1][xrow] = xv.y;
        Xs[xk4 + 2][xrow] = xv.z; Xs[xk4 + 3][xrow] = xv.w;

        Wu[wk0 + 0][wrow]  = u0.x; Wu[wk0 + 1][wrow]  = u0.y;
        Wu[wk0 + 2][wrow]  = u0.z; Wu[wk0 + 3][wrow]  = u0.w;
        Wu[wk0 + 16][wrow] = u1.x; Wu[wk0 + 17][wrow] = u1.y;
        Wu[wk0 + 18][wrow] = u1.z; Wu[wk0 + 19][wrow] = u1.w;

        Wg[wk0 + 0][wrow]  = g0.x; Wg[wk0 + 1][wrow]  = g0.y;
        Wg[wk0 + 2][wrow]  = g0.z; Wg[wk0 + 3][wrow]  = g0.w;
        Wg[wk0 + 16][wrow] = g1.x; Wg[wk0 + 17][wrow] = g1.y;
        Wg[wk0 + 18][wrow] = g1.z; Wg[wk0 + 19][wrow] = g1.w;

        __syncthreads();

#pragma unroll 8
        for (int k = 0; k < 32; k++) {
            float4 xq = *(const float4*)&Xs[k][4 * mg];   // broadcast within warp
            u64 wu = *(const u64*)&Wu[k][2 * ng];
            u64 wg = *(const u64*)&Wg[k][2 * ng];
            u64 x0 = pack2(xq.x, xq.x);
            u64 x1 = pack2(xq.y, xq.y);
            u64 x2 = pack2(xq.z, xq.z);
            u64 x3 = pack2(xq.w, xq.w);
            ffma2(au[0], x0, wu); ffma2(ag[0], x0, wg);
            ffma2(au[1], x1, wu); ffma2(ag[1], x1, wg);
            ffma2(au[2], x2, wu); ffma2(ag[2], x2, wg);
            ffma2(au[3], x3, wu); ffma2(ag[3], x3, wg);
        }
        __syncthreads();
    }

#pragma unroll
    for (int j = 0; j < 4; j++) {
        int m = 4 * mg + j;
        if (m0 + m < cnt) {
            float2 u = unpack2(au[j]);
            float2 g = unpack2(ag[j]);
            float2 o;
            o.x = (u.x / (1.0f + __expf(-u.x))) * g.x;   // silu(up) * gate
            o.y = (u.y / (1.0f + __expf(-u.y))) * g.y;
            *(float2*)&g_act[e][m0 + m][n0 + 2 * ng] = o;
        }
    }
}

// ---------------- kernel 3: fc2 + scaled scatter-add ---------------------------
// grid: (H/128, ceil(T/32), NE), block 256
// BM=32 tokens, BN=128 hidden channels, BK=32, K=IN=4096.
__global__ __launch_bounds__(256) void fc2_kernel(const float* __restrict__ w2,
                                                  float* __restrict__ out) {
    int e   = blockIdx.z;
    int cnt = g_cnt[e];
    int m0  = blockIdx.y * 32;
    if (m0 >= cnt) return;
    int n0  = blockIdx.x * 128;

    __shared__ __align__(16) float Xs[32][36];    // [k][m]
    __shared__ __align__(16) float Ws[32][132];   // [k][n]
    __shared__ int   toks[32];
    __shared__ float coefs[32];

    int tid = threadIdx.x;
    if (tid < 32) {
        int mm = m0 + tid;
        toks[tid]  = (mm < cnt) ? g_tok[e][mm]  : 0;
        coefs[tid] = (mm < cnt) ? g_coef[e][mm] : 0.f;
    }
    __syncthreads();

    const float* w2e = w2 + (size_t)e * H * IN;

    int xrow = tid >> 3;            // m slot: 0..31
    int xk4  = (tid & 7) * 4;
    bool xok = (m0 + xrow < cnt);
    const float* xsrc = &g_act[e][m0 + xrow][xk4];

    int wrow = tid >> 1;            // h row: 0..127
    int wkb  = (tid & 1) * 16;      // k base 0 or 16
    const float* wsrc = w2e + (size_t)(n0 + wrow) * IN + wkb;

    int mg = tid >> 5;              // 4-token group
    int ng = tid & 31;              // n quad: n = 4ng..4ng+3

    u64 acc[4][2] = {{0ull,0ull},{0ull,0ull},{0ull,0ull},{0ull,0ull}};

    for (int k0 = 0; k0 < IN; k0 += 32) {
        float4 xv = xok ? *(const float4*)(xsrc + k0) : make_float4(0.f,0.f,0.f,0.f);
        float4 a0 = *(const float4*)(wsrc + k0);
        float4 a1 = *(const float4*)(wsrc + k0 + 4);
        float4 a2 = *(const float4*)(wsrc + k0 + 8);
        float4 a3 = *(const float4*)(wsrc + k0 + 12);

        Xs[xk4 + 0][xrow] = xv.x; Xs[xk4 + 1][xrow] = xv.y;
        Xs[xk4 + 2][xrow] = xv.z; Xs[xk4 + 3][xrow] = xv.w;

        Ws[wkb + 0][wrow]  = a0.x; Ws[wkb + 1][wrow]  = a0.y;
        Ws[wkb + 2][wrow]  = a0.z; Ws[wkb + 3][wrow]  = a0.w;
        Ws[wkb + 4][wrow]  = a1.x; Ws[wkb + 5][wrow]  = a1.y;
        Ws[wkb + 6][wrow]  = a1.z; Ws[wkb + 7][wrow]  = a1.w;
        Ws[wkb + 8][wrow]  = a2.x; Ws[wkb + 9][wrow]  = a2.y;
        Ws[wkb + 10][wrow] = a2.z; Ws[wkb + 11][wrow] = a2.w;
        Ws[wkb + 12][wrow] = a3.x; Ws[wkb + 13][wrow] = a3.y;
        Ws[wkb + 14][wrow] = a3.z; Ws[wkb + 15][wrow] = a3.w;

        __syncthreads();

#pragma unroll 8
        for (int k = 0; k < 32; k++) {
            float4 xq = *(const float4*)&Xs[k][4 * mg];   // broadcast
            float4 wq = *(const float4*)&Ws[k][4 * ng];   // conflict-free 512B
            u64 wlo = pack2(wq.x, wq.y);
            u64 whi = pack2(wq.z, wq.w);
            u64 x0 = pack2(xq.x, xq.x);
            u64 x1 = pack2(xq.y, xq.y);
            u64 x2 = pack2(xq.z, xq.z);
            u64 x3 = pack2(xq.w, xq.w);
            ffma2(acc[0][0], x0, wlo); ffma2(acc[0][1], x0, whi);
            ffma2(acc[1][0], x1, wlo); ffma2(acc[1][1], x1, whi);
            ffma2(acc[2][0], x2, wlo); ffma2(acc[2][1], x2, whi);
            ffma2(acc[3][0], x3, wlo); ffma2(acc[3][1], x3, whi);
        }
        __syncthreads();
    }

#pragma unroll
    for (int j = 0; j < 4; j++) {
        int m = 4 * mg + j;
        if (m0 + m < cnt) {
            int   t = toks[m];
            float c = coefs[m];
            float2 a = unpack2(acc[j][0]);
            float2 b = unpack2(acc[j][1]);
            float* o = out + (size_t)t * H + n0 + 4 * ng;
            atomicAdd(o + 0, c * a.x);
            atomicAdd(o + 1, c * a.y);
            atomicAdd(o + 2, c * b.x);
            atomicAdd(o + 3, c * b.y);
        }
    }
}

// ---------------- launch ----------------
extern "C" void kernel_launch(void* const* d_in, const int* in_sizes, int n_in,
                              void* d_out, int out_size) {
    const float* x       = (const float*)d_in[0];   // [128, 1024]
    const float* routing = (const float*)d_in[1];   // [128, 8]
    const float* w1      = (const float*)d_in[2];   // [8, 8192, 1024]
    const float* w2      = (const float*)d_in[3];   // [8, 1024, 4096]
    float* out = (float*)d_out;                     // [128, 1024]

    zero_out_kernel<<<(T * H + 255) / 256, 256>>>(out);
    route_kernel<<<1, T>>>(routing);
    fc1_kernel<<<dim3(IN / 64, (T + 31) / 32, NE), 256>>>(x, w1);
    fc2_kernel<<<dim3(H / 128, (T + 31) / 32, NE), 256>>>(w2, out);
}

// round 3
// speedup vs baseline: 1.0027x; 1.0027x over previous
#include <cuda_runtime.h>
#include <math.h>

#define T   128
#define H   1024
#define IN  4096
#define NE  8

typedef unsigned long long u64;

// ---------------- device-global scratch (no runtime allocation) ----------------
__device__ int   g_cnt[NE];
__device__ int   g_tok[NE][T];
__device__ float g_coef[NE][T];
__device__ float g_act[NE][T][IN];   // 16.8 MB fp32 scratch for swiglu activations

// ---------------- packed fp32x2 helpers (FFMA2 path — 2x fp32 throughput) ------
__device__ __forceinline__ void ffma2(u64 &acc, u64 a, u64 b) {
    asm("fma.rn.f32x2 %0, %1, %2, %0;" : "+l"(acc) : "l"(a), "l"(b));
}
__device__ __forceinline__ u64 pack2(float x, float y) {
    u64 r; asm("mov.b64 %0, {%1, %2};" : "=l"(r) : "f"(x), "f"(y)); return r;
}
__device__ __forceinline__ float2 unpack2(u64 v) {
    float2 r; asm("mov.b64 {%0, %1}, %2;" : "=f"(r.x), "=f"(r.y) : "l"(v)); return r;
}

// ---------------- kernel 0: zero the output ----------------
__global__ void zero_out_kernel(float* __restrict__ out) {
    int i = blockIdx.x * blockDim.x + threadIdx.x;
    if (i < T * H) out[i] = 0.0f;
}

// ---------------- kernel 1: routing (top-2 + renormalize, build expert lists) ----
__global__ void route_kernel(const float* __restrict__ routing) {
    __shared__ int s_cnt[NE];
    int t = threadIdx.x;
    if (t < NE) s_cnt[t] = 0;
    __syncthreads();

    float r[NE];
#pragma unroll
    for (int e = 0; e < NE; e++) r[e] = routing[t * NE + e];

    // top-1 (lowest index wins ties via strict >)
    int i0 = 0;
#pragma unroll
    for (int e = 1; e < NE; e++) if (r[e] > r[i0]) i0 = e;
    // top-2
    int i1 = (i0 == 0) ? 1 : 0;
#pragma unroll
    for (int e = 0; e < NE; e++) if (e != i0 && r[e] > r[i1]) i1 = e;

    // softmax + renormalize over top-2 collapses to a 2-way sigmoid
    float d  = expf(r[i1] - r[i0]);   // <= 1
    float s0 = 1.0f / (1.0f + d);
    float s1 = d / (1.0f + d);

    int p0 = atomicAdd(&s_cnt[i0], 1);
    int p1 = atomicAdd(&s_cnt[i1], 1);
    g_tok[i0][p0]  = t;  g_coef[i0][p0] = s0;
    g_tok[i1][p1]  = t;  g_coef[i1][p1] = s1;

    __syncthreads();
    if (t < NE) g_cnt[t] = s_cnt[t];
}

// ---------------- kernel 2: fc1 + swiglu --------------------------------------
// grid: (IN/64, ceil(T/32), NE), block 256
// BM=32 tokens, BN=64 inter channels (=> 128 weight rows: up + gate), BK=32.
// Shared tiles are k-major so the compute loop is conflict-free:
//   per k per thread: 1 LDS.128 (x, broadcast) + 2 LDS.64 (wu, wg) + 4 packs + 8 FFMA2
__global__ __launch_bounds__(256) void fc1_kernel(const float* __restrict__ x,
                                                  const float* __restrict__ w1) {
    int e   = blockIdx.z;
    int cnt = g_cnt[e];
    int m0  = blockIdx.y * 32;
    if (m0 >= cnt) return;
    int n0  = blockIdx.x * 64;

    __shared__ __align__(16) float Xs[32][36];   // [k][m]
    __shared__ __align__(16) float Wu[32][68];   // [k][n]  (up rows n0..n0+63)
    __shared__ __align__(16) float Wg[32][68];   // [k][n]  (gate rows IN+n0..)
    __shared__ int toks[32];

    int tid = threadIdx.x;
    if (tid < 32) toks[tid] = (m0 + tid < cnt) ? g_tok[e][m0 + tid] : -1;
    __syncthreads();

    const float* w1e = w1 + (size_t)e * (2 * IN) * H;

    // loader roles
    int xrow = tid >> 3;            // m: 0..31
    int xk4  = (tid & 7) * 4;       // k: 0,4,...,28
    int xtok = toks[xrow];
    const float* xsrc = (xtok >= 0) ? (x + (size_t)xtok * H + xk4) : 0;

    int wrow = tid >> 2;            // n: 0..63
    int wk0  = (tid & 3) * 4;       // k: loads wk0 and wk0+16
    const float* usrc = w1e + (size_t)(n0 + wrow) * H + wk0;
    const float* gsrc = w1e + (size_t)(IN + n0 + wrow) * H + wk0;

    // compute roles
    int mg = tid >> 5;              // warp id -> m group (4 tokens)
    int ng = tid & 31;              // n pair: n = 2ng, 2ng+1

    u64 au[4] = {0ull, 0ull, 0ull, 0ull};
    u64 ag[4] = {0ull, 0ull, 0ull, 0ull};

    for (int k0 = 0; k0 < H; k0 += 32) {
        float4 xv = make_float4(0.f, 0.f, 0.f, 0.f);
        if (xsrc) xv = *(const float4*)(xsrc + k0);
        float4 u0 = *(const float4*)(usrc + k0);
        float4 u1 = *(const float4*)(usrc + k0 + 16);
        float4 g0 = *(const float4*)(gsrc + k0);
        float4 g1 = *(const float4*)(gsrc + k0 + 16);

        Xs[xk4 + 0][xrow] = xv.x; Xs[xk4 + 1][xrow] = xv.y;
        Xs[xk4 + 2][xrow] = xv.z; Xs[xk4 + 3][xrow] = xv.w;

        Wu[wk0 + 0][wrow]  = u0.x; Wu[wk0 + 1][wrow]  = u0.y;
        Wu[wk0 + 2][wrow]  = u0.z; Wu[wk0 + 3][wrow]  = u0.w;
        Wu[wk0 + 16][wrow] = u1.x; Wu[wk0 + 17][wrow] = u1.y;
        Wu[wk0 + 18][wrow] = u1.z; Wu[wk0 + 19][wrow] = u1.w;

        Wg[wk0 + 0][wrow]  = g0.x; Wg[wk0 + 1][wrow]  = g0.y;
        Wg[wk0 + 2][wrow]  = g0.z; Wg[wk0 + 3][wrow]  = g0.w;
        Wg[wk0 + 16][wrow] = g1.x; Wg[wk0 + 17][wrow] = g1.y;
        Wg[wk0 + 18][wrow] = g1.z; Wg[wk0 + 19][wrow] = g1.w;

        __syncthreads();

#pragma unroll 8
        for (int k = 0; k < 32; k++) {
            float4 xq = *(const float4*)&Xs[k][4 * mg];   // broadcast within warp
            u64 wu = *(const u64*)&Wu[k][2 * ng];
            u64 wg = *(const u64*)&Wg[k][2 * ng];
            u64 x0 = pack2(xq.x, xq.x);
            u64 x1 = pack2(xq.y, xq.y);
            u64 x2 = pack2(xq.z, xq.z);
            u64 x3 = pack2(xq.w, xq.w);
            ffma2(au[0], x0, wu); ffma2(ag[0], x0, wg);
            ffma2(au[1], x1, wu); ffma2(ag[1], x1, wg);
            ffma2(au[2], x2, wu); ffma2(ag[2], x2, wg);
            ffma2(au[3], x3, wu); ffma2(ag[3], x3, wg);
        }
        __syncthreads();
    }

#pragma unroll
    for (int j = 0; j < 4; j++) {
        int m = 4 * mg + j;
        if (m0 + m < cnt) {
            float2 u = unpack2(au[j]);
            float2 g = unpack2(ag[j]);
            float2 o;
            o.x = (u.x / (1.0f + __expf(-u.x))) * g.x;   // silu(up) * gate
            o.y = (u.y / (1.0f + __expf(-u.y))) * g.y;
            *(float2*)&g_act[e][m0 + m][n0 + 2 * ng] = o;
        }
    }
}

// ---------------- kernel 3: fc2 + scaled scatter-add ---------------------------
// grid: (H/128, ceil(T/32), NE), block 256
// BM=32 tokens, BN=128 hidden channels, BK=32, K=IN=4096.
__global__ __launch_bounds__(256) void fc2_kernel(const float* __restrict__ w2,
                                                  float* __restrict__ out) {
    int e   = blockIdx.z;
    int cnt = g_cnt[e];
    int m0  = blockIdx.y * 32;
    if (m0 >= cnt) return;
    int n0  = blockIdx.x * 128;

    __shared__ __align__(16) float Xs[32][36];    // [k][m]
    __shared__ __align__(16) float Ws[32][132];   // [k][n]
    __shared__ int   toks[32];
    __shared__ float coefs[32];

    int tid = threadIdx.x;
    if (tid < 32) {
        int mm = m0 + tid;
        toks[tid]  = (mm < cnt) ? g_tok[e][mm]  : 0;
        coefs[tid] = (mm < cnt) ? g_coef[e][mm] : 0.f;
    }
    __syncthreads();

    const float* w2e = w2 + (size_t)e * H * IN;

    int xrow = tid >> 3;            // m slot: 0..31
    int xk4  = (tid & 7) * 4;
    bool xok = (m0 + xrow < cnt);
    const float* xsrc = &g_act[e][m0 + xrow][xk4];

    int wrow = tid >> 1;            // h row: 0..127
    int wkb  = (tid & 1) * 16;      // k base 0 or 16
    const float* wsrc = w2e + (size_t)(n0 + wrow) * IN + wkb;

    int mg = tid >> 5;              // 4-token group
    int ng = tid & 31;              // n quad: n = 4ng..4ng+3

    u64 acc[4][2] = {{0ull,0ull},{0ull,0ull},{0ull,0ull},{0ull,0ull}};

    for (int k0 = 0; k0 < IN; k0 += 32) {
        float4 xv = xok ? *(const float4*)(xsrc + k0) : make_float4(0.f,0.f,0.f,0.f);
        float4 a0 = *(const float4*)(wsrc + k0);
        float4 a1 = *(const float4*)(wsrc + k0 + 4);
        float4 a2 = *(const float4*)(wsrc + k0 + 8);
        float4 a3 = *(const float4*)(wsrc + k0 + 12);

        Xs[xk4 + 0][xrow] = xv.x; Xs[xk4 + 1][xrow] = xv.y;
        Xs[xk4 + 2][xrow] = xv.z; Xs[xk4 + 3][xrow] = xv.w;

        Ws[wkb + 0][wrow]  = a0.x; Ws[wkb + 1][wrow]  = a0.y;
        Ws[wkb + 2][wrow]  = a0.z; Ws[wkb + 3][wrow]  = a0.w;
        Ws[wkb + 4][wrow]  = a1.x; Ws[wkb + 5][wrow]  = a1.y;
        Ws[wkb + 6][wrow]  = a1.z; Ws[wkb + 7][wrow]  = a1.w;
        Ws[wkb + 8][wrow]  = a2.x; Ws[wkb + 9][wrow]  = a2.y;
        Ws[wkb + 10][wrow] = a2.z; Ws[wkb + 11][wrow] = a2.w;
        Ws[wkb + 12][wrow] = a3.x; Ws[wkb + 13][wrow] = a3.y;
        Ws[wkb + 14][wrow] = a3.z; Ws[wkb + 15][wrow] = a3.w;

        __syncthreads();

#pragma unroll 8
        for (int k = 0; k < 32; k++) {
            float4 xq = *(const float4*)&Xs[k][4 * mg];   // broadcast
            float4 wq = *(const float4*)&Ws[k][4 * ng];   // conflict-free 512B
            u64 wlo = pack2(wq.x, wq.y);
            u64 whi = pack2(wq.z, wq.w);
            u64 x0 = pack2(xq.x, xq.x);
            u64 x1 = pack2(xq.y, xq.y);
            u64 x2 = pack2(xq.z, xq.z);
            u64 x3 = pack2(xq.w, xq.w);
            ffma2(acc[0][0], x0, wlo); ffma2(acc[0][1], x0, whi);
            ffma2(acc[1][0], x1, wlo); ffma2(acc[1][1], x1, whi);
            ffma2(acc[2][0], x2, wlo); ffma2(acc[2][1], x2, whi);
            ffma2(acc[3][0], x3, wlo); ffma2(acc[3][1], x3, whi);
        }
        __syncthreads();
    }

#pragma unroll
    for (int j = 0; j < 4; j++) {
        int m = 4 * mg + j;
        if (m0 + m < cnt) {
            int   t = toks[m];
            float c = coefs[m];
            float2 a = unpack2(acc[j][0]);
            float2 b = unpack2(acc[j][1]);
            float* o = out + (size_t)t * H + n0 + 4 * ng;
            atomicAdd(o + 0, c * a.x);
            atomicAdd(o + 1, c * a.y);
            atomicAdd(o + 2, c * b.x);
            atomicAdd(o + 3, c * b.y);
        }
    }
}

// ---------------- launch ----------------
extern "C" void kernel_launch(void* const* d_in, const int* in_sizes, int n_in,
                              void* d_out, int out_size) {
    const float* x       = (const float*)d_in[0];   // [128, 1024]
    const float* routing = (const float*)d_in[1];   // [128, 8]
    const float* w1      = (const float*)d_in[2];   // [8, 8192, 1024]
    const float* w2      = (const float*)d_in[3];   // [8, 1024, 4096]
    float* out = (float*)d_out;                     // [128, 1024]

    zero_out_kernel<<<(T * H + 255) / 256, 256>>>(out);
    route_kernel<<<1, T>>>(routing);
    fc1_kernel<<<dim3(IN / 64, (T + 31) / 32, NE), 256>>>(x, w1);
    fc2_kernel<<<dim3(H / 128, (T + 31) / 32, NE), 256>>>(w2, out);
}